// round 1
// baseline (speedup 1.0000x reference)
#include <cuda_runtime.h>

typedef unsigned long long u64;

#define RAD 4
#define TX 64
#define TY 16
#define BW 32
#define NTHREADS (BW * TY)
#define HALO_W (TX + 2 * RAD)   // 72
#define HALO_H (TY + 2 * RAD)   // 24
#define PITCH  HALO_W           // 72 floats (even -> 8B pair alignment holds)
#define PLANE  (HALO_H * PITCH) // 1728 floats
#define IMG_H 1024
#define IMG_W 1024
#define IMG_B 8

// C1 = (-0.5 / (75*75)) * log2(e)  — shared by color and space terms
#define C1F (-1.2823955919013e-04f)
#define ABSM 0x7FFFFFFF7FFFFFFFULL
#define SGNM 0x8000000080000000ULL

__device__ __forceinline__ u64 f2add(u64 a, u64 b) {
    u64 r; asm("add.rn.f32x2 %0, %1, %2;" : "=l"(r) : "l"(a), "l"(b)); return r;
}
__device__ __forceinline__ u64 f2mul(u64 a, u64 b) {
    u64 r; asm("mul.rn.f32x2 %0, %1, %2;" : "=l"(r) : "l"(a), "l"(b)); return r;
}
__device__ __forceinline__ u64 f2fma(u64 a, u64 b, u64 c) {
    u64 r; asm("fma.rn.f32x2 %0, %1, %2, %3;" : "=l"(r) : "l"(a), "l"(b), "l"(c)); return r;
}
__device__ __forceinline__ u64 f2pack(float x, float y) {
    u64 r; asm("mov.b64 %0, {%1, %2};" : "=l"(r) : "f"(x), "f"(y)); return r;
}
__device__ __forceinline__ float2 f2unpack(u64 v) {
    float2 r; asm("mov.b64 {%0, %1}, %2;" : "=f"(r.x), "=f"(r.y) : "l"(v)); return r;
}
__device__ __forceinline__ float fex2(float x) {
    float r; asm("ex2.approx.f32 %0, %1;" : "=f"(r) : "f"(x)); return r;
}
__device__ __forceinline__ float frcp(float x) {
    float r; asm("rcp.approx.f32 %0, %1;" : "=f"(r) : "f"(x)); return r;
}
__device__ __forceinline__ int refl(int i, int n) {
    if (i < 0) i = -i;
    if (i >= n) i = 2 * n - 2 - i;
    return i;
}

__global__ void __launch_bounds__(NTHREADS)
bilateral_kernel(const float* __restrict__ in, float* __restrict__ out)
{
    // planes 0..2: r,g,b aligned copies; planes 3..5: shifted-by-one copies
    // (odd[j] = V[j+1]) so odd-dx pixel pairs are 8B-aligned LDS.64 too.
    __shared__ __align__(16) float sm[6 * PLANE];

    const int b  = blockIdx.z;
    const int x0 = blockIdx.x * TX;
    const int y0 = blockIdx.y * TY;
    const int tid = threadIdx.y * BW + threadIdx.x;
    const float* img = in + (size_t)b * ((size_t)IMG_H * IMG_W * 3);

    // ---- cooperative halo load (reflect padding), deinterleave to planes ----
    for (int i = tid; i < HALO_H * HALO_W; i += NTHREADS) {
        int lr = i / HALO_W;
        int lx = i - lr * HALO_W;
        int gy = refl(y0 + lr - RAD, IMG_H);
        int gx = refl(x0 + lx - RAD, IMG_W);
        const float* p = img + ((size_t)gy * IMG_W + gx) * 3;
        float vr = p[0], vg = p[1], vb = p[2];
        int e = lr * PITCH + lx;
        sm[0 * PLANE + e] = vr;
        sm[1 * PLANE + e] = vg;
        sm[2 * PLANE + e] = vb;
        if (lx > 0) {
            sm[3 * PLANE + e - 1] = vr;
            sm[4 * PLANE + e - 1] = vg;
            sm[5 * PLANE + e - 1] = vb;
        }
    }
    __syncthreads();

    // ---- per-thread: two adjacent output pixels, all math in f32x2 ----
    const int clx  = RAD + 2 * threadIdx.x;   // even
    const int crow = RAD + threadIdx.y;
    const float* pb = sm + crow * PITCH + clx;

    u64 cr = *(const u64*)(pb + 0 * PLANE);
    u64 cg = *(const u64*)(pb + 1 * PLANE);
    u64 cb = *(const u64*)(pb + 2 * PLANE);
    const u64 ncr = cr ^ SGNM, ncg = cg ^ SGNM, ncb = cb ^ SGNM;
    const u64 c1c1 = f2pack(C1F, C1F);

    u64 ar = 0ULL, ag = 0ULL, ab = 0ULL, ad = 0ULL;

#pragma unroll
    for (int dy = -RAD; dy <= RAD; ++dy) {
#pragma unroll
        for (int dx = -RAD; dx <= RAD; ++dx) {
            if (dy * dy + dx * dx > RAD * RAD) continue;
            const float lsw = C1F * (float)(dy * dy + dx * dx); // log2(spatial w)
            const u64 lswp = f2pack(lsw, lsw);                  // CSE-hoisted (10 distinct)

            int pl, off;
            if ((dx & 1) == 0) { pl = 0; off = dy * PITCH + dx; }
            else               { pl = 3; off = dy * PITCH + dx - 1; }

            u64 nr = *(const u64*)(pb + (pl + 0) * PLANE + off);
            u64 ng = *(const u64*)(pb + (pl + 1) * PLANE + off);
            u64 nb = *(const u64*)(pb + (pl + 2) * PLANE + off);

            u64 dr = f2add(nr, ncr);
            u64 dg = f2add(ng, ncg);
            u64 db = f2add(nb, ncb);
            u64 s  = f2add(dr & ABSM, dg & ABSM);
            s      = f2add(s, db & ABSM);
            u64 yy = f2mul(s, s);
            u64 lw = f2fma(yy, c1c1, lswp);     // log2(w) = C1*(diff^2 + r2)
            float2 lwf = f2unpack(lw);
            u64 w = f2pack(fex2(lwf.x), fex2(lwf.y));

            ar = f2fma(w, nr, ar);
            ag = f2fma(w, ng, ag);
            ab = f2fma(w, nb, ab);
            ad = f2add(ad, w);
        }
    }

    float2 R2 = f2unpack(ar), G2 = f2unpack(ag), B2 = f2unpack(ab), D2 = f2unpack(ad);
    float i0 = frcp(D2.x), i1 = frcp(D2.y);

    const int gx = x0 + 2 * threadIdx.x;
    const int gy = y0 + threadIdx.y;
    float* o = out + (((size_t)b * IMG_H + gy) * (size_t)IMG_W + gx) * 3;
    // 6 contiguous floats, 8B-aligned (gx even) -> 3x STG.64
    ((float2*)o)[0] = make_float2(R2.x * i0, G2.x * i0);
    ((float2*)o)[1] = make_float2(B2.x * i0, R2.y * i1);
    ((float2*)o)[2] = make_float2(G2.y * i1, B2.y * i1);
}

extern "C" void kernel_launch(void* const* d_in, const int* in_sizes, int n_in,
                              void* d_out, int out_size)
{
    (void)in_sizes; (void)n_in; (void)out_size;
    const float* in = (const float*)d_in[0];
    float* out = (float*)d_out;
    dim3 grid(IMG_W / TX, IMG_H / TY, IMG_B);
    dim3 block(BW, TY);
    bilateral_kernel<<<grid, block>>>(in, out);
}